// round 6
// baseline (speedup 1.0000x reference)
#include <cuda_runtime.h>
#include <math.h>

#define N_NODES 100000
#define N_EDGES 3200000
#define IN_CH   256
#define HC      128   // HEADS*OUT_CH flattened
#define OUT_CH  64
#define NEG_SLOPE 0.2f

// ---------------- scratch (static device allocations are allowed) -----------
__device__ float g_x[(size_t)N_NODES * HC];      // projected features, 51.2 MB
__device__ float4 g_att[N_NODES];                // (a_src0, a_src1, a_dst0, a_dst1)
__device__ int g_count[N_NODES];
__device__ int g_offset[N_NODES];
__device__ int g_cursor[N_NODES];
__device__ int g_sorted_src[N_EDGES];            // src idx sorted by dst

// ---------------- zero counts ----------------
__global__ void zero_counts_kernel() {
    int i = blockIdx.x * blockDim.x + threadIdx.x;
    if (i < N_NODES) g_count[i] = 0;
}

// ---------------- SGEMM: x = z @ W  (100000x256 @ 256x128) ----------------
#define BM 128
#define BN 128
#define BK 16

__global__ __launch_bounds__(256) void gemm_kernel(const float* __restrict__ Z,
                                                   const float* __restrict__ Wm) {
    __shared__ float As[BK][BM];   // transposed A tile
    __shared__ float Bs[BK][BN];
    int tid = threadIdx.x;
    int row0 = blockIdx.x * BM;

    int a_r = tid >> 2;            // 0..63
    int a_c = (tid & 3) << 2;      // 0,4,8,12
    int b_r = tid >> 5;            // 0..7
    int b_c = (tid & 31) << 2;     // 0..124

    int tx = tid & 15;             // column group
    int ty = tid >> 4;             // row group

    float acc[8][8];
#pragma unroll
    for (int i = 0; i < 8; i++)
#pragma unroll
        for (int j = 0; j < 8; j++) acc[i][j] = 0.f;

    for (int k0 = 0; k0 < IN_CH; k0 += BK) {
#pragma unroll
        for (int i = 0; i < 2; i++) {
            int r = row0 + a_r + i * 64;
            float4 v = make_float4(0.f, 0.f, 0.f, 0.f);
            if (r < N_NODES)
                v = *(const float4*)&Z[(size_t)r * IN_CH + k0 + a_c];
            As[a_c + 0][a_r + i * 64] = v.x;
            As[a_c + 1][a_r + i * 64] = v.y;
            As[a_c + 2][a_r + i * 64] = v.z;
            As[a_c + 3][a_r + i * 64] = v.w;
        }
#pragma unroll
        for (int i = 0; i < 2; i++) {
            int r = k0 + b_r + i * 8;
            *(float4*)&Bs[b_r + i * 8][b_c] = *(const float4*)&Wm[(size_t)r * BN + b_c];
        }
        __syncthreads();
#pragma unroll
        for (int k = 0; k < BK; k++) {
            float a[8], b[8];
#pragma unroll
            for (int i = 0; i < 4; i++) {
                a[i]     = As[k][ty * 4 + i];
                a[i + 4] = As[k][64 + ty * 4 + i];
            }
#pragma unroll
            for (int j = 0; j < 4; j++) {
                b[j]     = Bs[k][tx * 4 + j];
                b[j + 4] = Bs[k][64 + tx * 4 + j];
            }
#pragma unroll
            for (int i = 0; i < 8; i++)
#pragma unroll
                for (int j = 0; j < 8; j++)
                    acc[i][j] += a[i] * b[j];
        }
        __syncthreads();
    }

#pragma unroll
    for (int i = 0; i < 8; i++) {
        int r = row0 + ((i < 4) ? (ty * 4 + i) : (64 + ty * 4 + (i - 4)));
        if (r < N_NODES) {
            float* orow = &g_x[(size_t)r * HC];
            *(float4*)&orow[tx * 4]      = make_float4(acc[i][0], acc[i][1], acc[i][2], acc[i][3]);
            *(float4*)&orow[64 + tx * 4] = make_float4(acc[i][4], acc[i][5], acc[i][6], acc[i][7]);
        }
    }
}

// ---------------- per-node attention dots: a_src / a_dst per head ----------
__global__ void att_kernel(const float* __restrict__ att_src,
                           const float* __restrict__ att_dst) {
    int warp = (blockIdx.x * blockDim.x + threadIdx.x) >> 5;
    if (warp >= N_NODES) return;
    int lane = threadIdx.x & 31;

    float4 xv  = *(const float4*)&g_x[(size_t)warp * HC + lane * 4];
    float4 as4 = __ldg((const float4*)&att_src[lane * 4]);  // flat (H*C)=128
    float4 ad4 = __ldg((const float4*)&att_dst[lane * 4]);

    float ps = xv.x * as4.x + xv.y * as4.y + xv.z * as4.z + xv.w * as4.w;
    float pd = xv.x * ad4.x + xv.y * ad4.y + xv.z * ad4.z + xv.w * ad4.w;
    // reduce within each 16-lane half (one head per half)
#pragma unroll
    for (int off = 8; off; off >>= 1) {
        ps += __shfl_xor_sync(0xffffffffu, ps, off);
        pd += __shfl_xor_sync(0xffffffffu, pd, off);
    }
    // FIX: execute these shuffles convergently (ALL lanes), not inside lane==0
    float ps16 = __shfl_sync(0xffffffffu, ps, 16);  // head-1 src dot
    float pd16 = __shfl_sync(0xffffffffu, pd, 16);  // head-1 dst dot
    if (lane == 0) {
        g_att[warp] = make_float4(ps, ps16, pd, pd16);
    }
}

// ------- histogram of dst (edge_index int32, row-split [src(E) | dst(E)]) --
__global__ void hist_kernel(const int* __restrict__ ei) {
    int e = blockIdx.x * blockDim.x + threadIdx.x;
    if (e < N_EDGES) {
        int d = __ldg(&ei[N_EDGES + e]);
        if ((unsigned)d < (unsigned)N_NODES)
            atomicAdd(&g_count[d], 1);
    }
}

// ---------------- 1-block, 2-pass exclusive scan of counts ----------------
__global__ void scan_kernel() {
    __shared__ int sh[1024];
    int t = threadIdx.x;
    const int CH = (N_NODES + 1023) / 1024;   // 98
    int begin = t * CH;
    int end = begin + CH; if (end > N_NODES) end = N_NODES;
    int sum = 0;
    for (int i = begin; i < end; i++) sum += g_count[i];
    sh[t] = sum;
    __syncthreads();
    // Hillis-Steele inclusive scan (barriers are uniform across all threads)
    for (int off = 1; off < 1024; off <<= 1) {
        int v = (t >= off) ? sh[t - off] : 0;
        __syncthreads();
        sh[t] += v;
        __syncthreads();
    }
    int run = (t == 0) ? 0 : sh[t - 1];
    for (int i = begin; i < end; i++) {
        g_offset[i] = run;
        g_cursor[i] = run;
        run += g_count[i];
    }
}

// ---------------- counting-sort scatter of src indices ----------------
__global__ void scatter_kernel(const int* __restrict__ ei) {
    int e = blockIdx.x * blockDim.x + threadIdx.x;
    if (e < N_EDGES) {
        int d = __ldg(&ei[N_EDGES + e]);
        int s = __ldg(&ei[e]);
        if ((unsigned)d < (unsigned)N_NODES && (unsigned)s < (unsigned)N_NODES) {
            int pos = atomicAdd(&g_cursor[d], 1);
            g_sorted_src[pos] = s;
        }
    }
}

// ---------------- aggregation: one warp per dst node, online softmax ------
__global__ __launch_bounds__(256) void aggregate_kernel(const float* __restrict__ bias,
                                                        float* __restrict__ out) {
    int warp = (blockIdx.x * blockDim.x + threadIdx.x) >> 5;
    if (warp >= N_NODES) return;
    int lane = threadIdx.x & 31;
    int d = warp;

    float4 attv = g_att[d];                 // (as0, as1, ad0, ad1)
    int h = lane >> 4;
    float adst = h ? attv.w : attv.z;

    // self-loop initializes the online softmax state
    float lself = (h ? attv.y : attv.x) + adst;
    lself = fmaxf(lself, NEG_SLOPE * lself);        // leaky relu
    float m = lself;
    float s = 1.0f;
    const float4* x4 = (const float4*)g_x;
    float4 acc = x4[(size_t)d * 32 + lane];         // weight exp(0)=1

    int base = g_offset[d];
    int cnt  = g_count[d];
    const float2* att2 = (const float2*)g_att;      // att2[2*n] = (as0, as1)

    for (int i = 0; i < cnt; i++) {
        int sidx = g_sorted_src[base + i];
        float2 asv = att2[(size_t)sidx * 2];
        float l = (h ? asv.y : asv.x) + adst;
        l = fmaxf(l, NEG_SLOPE * l);

        float4 xv = x4[(size_t)sidx * 32 + lane];

        float nm = fmaxf(m, l);
        float f  = __expf(m - nm);
        float w  = __expf(l - nm);
        m = nm;
        s = s * f + w;
        acc.x = acc.x * f + w * xv.x;
        acc.y = acc.y * f + w * xv.y;
        acc.z = acc.z * f + w * xv.z;
        acc.w = acc.w * f + w * xv.w;
    }

    float inv = 1.0f / (2.0f * s);          // /s then mean over 2 heads
    acc.x *= inv; acc.y *= inv; acc.z *= inv; acc.w *= inv;

    // combine heads: lane j (head0, out ch 4j) + lane j+16 (head1, out ch 4j)
    float ox = __shfl_down_sync(0xffffffffu, acc.x, 16);
    float oy = __shfl_down_sync(0xffffffffu, acc.y, 16);
    float oz = __shfl_down_sync(0xffffffffu, acc.z, 16);
    float ow = __shfl_down_sync(0xffffffffu, acc.w, 16);
    if (lane < 16) {
        float4 b = __ldg((const float4*)&bias[lane * 4]);
        float4 r = make_float4(acc.x + ox + b.x, acc.y + oy + b.y,
                               acc.z + oz + b.z, acc.w + ow + b.w);
        *(float4*)&out[(size_t)d * OUT_CH + lane * 4] = r;
    }
}

// ---------------- launch ----------------
extern "C" void kernel_launch(void* const* d_in, const int* in_sizes, int n_in,
                              void* d_out, int out_size) {
    const float* z       = (const float*)d_in[0];
    const int*   ei      = (const int*)d_in[1];     // int32, row-split [src(E) | dst(E)]
    const float* Wm      = (const float*)d_in[2];
    const float* att_src = (const float*)d_in[3];
    const float* att_dst = (const float*)d_in[4];
    const float* bias    = (const float*)d_in[5];
    float* out = (float*)d_out;

    zero_counts_kernel<<<(N_NODES + 255) / 256, 256>>>();
    gemm_kernel<<<(N_NODES + BM - 1) / BM, 256>>>(z, Wm);
    att_kernel<<<(N_NODES * 32 + 255) / 256, 256>>>(att_src, att_dst);
    hist_kernel<<<(N_EDGES + 255) / 256, 256>>>(ei);
    scan_kernel<<<1, 1024>>>();
    scatter_kernel<<<(N_EDGES + 255) / 256, 256>>>(ei);
    aggregate_kernel<<<(N_NODES * 32 + 255) / 256, 256>>>(bias, out);
}